// round 6
// baseline (speedup 1.0000x reference)
#include <cuda_runtime.h>
#include <cuda_bf16.h>

// upfirdn2d: up=2, down=1, pad=(2,1), 4x4 separable FIR (rank-1: K = g x f).
// Input 2048 planes of 128x128 f32 -> Output 2048 planes of 256x256 f32.
//
// Per-dim half-phase taps (true conv on zero-inserted, padded signal):
//   even o: f[3]*x[o/2-1] + f[1]*x[o/2]
//   odd  o: f[2]*x[(o-1)/2] + f[0]*x[(o+1)/2]
// Horizontal half-conv per input row -> h[8] per lane, then vertical combine:
//   out row 2r   = g3*h(r-1) + h(r)          (g1 normalized to 1)
//   out row 2r+1 = g2*h(r)   + g0*h(r+1)
//
// One warp spans a FULL input row (32 lanes x float4 = 128 cols): horizontal
// halo is pure warp-shuffle; lanes 0/31 see the true zero pad. Each warp
// rolls down 16 rows, TWO rows per iteration (2 independent LDG.128 in
// flight -> 2x memory-level parallelism vs one-row rolling).

#define H   128
#define W   128
#define OW  256
#define RPW 16   // input rows per warp

__global__ __launch_bounds__(256) void fir_up2_kernel(
    const float* __restrict__ x,
    const float* __restrict__ kern,
    float* __restrict__ out)
{
    const int plane = blockIdx.x;
    const int warp  = threadIdx.x >> 5;
    const int lane  = threadIdx.x & 31;
    const int r0    = warp * RPW;          // 8 warps x 16 rows = 128
    const int c0    = lane * 4;            // input col of v.x

    const float* __restrict__ xp = x + (size_t)plane * (H * W);
    float* __restrict__ op = out + (size_t)plane * (OW * 2 * H);

    // taps (rank-1 factorization of the 4x4 kernel)
    const float f0 = __ldg(kern + 4 + 0);
    const float f1 = __ldg(kern + 4 + 1);
    const float f2 = __ldg(kern + 4 + 2);
    const float f3 = __ldg(kern + 4 + 3);
    const float inv = 1.0f / f1;
    const float g0 = __ldg(kern + 0 * 4 + 1) * inv;
    const float g2 = __ldg(kern + 2 * 4 + 1) * inv;
    const float g3 = __ldg(kern + 3 * 4 + 1) * inv;

    auto load_raw = [&](int r) -> float4 {
        if (r < 0 || r >= H) return make_float4(0.f, 0.f, 0.f, 0.f);
        return __ldcs((const float4*)(xp + r * W + c0));
    };

    // Horizontal half-convolution of one raw row -> 8 output-col values.
    auto hconv = [&](float4 v, float h[8]) {
        float m = __shfl_up_sync(0xffffffffu, v.w, 1);
        if (lane == 0) m = 0.0f;               // true left zero-pad
        float q = __shfl_down_sync(0xffffffffu, v.x, 1);
        if (lane == 31) q = 0.0f;              // true right zero-pad
        h[0] = f3 * m   + f1 * v.x;
        h[1] = f2 * v.x + f0 * v.y;
        h[2] = f3 * v.x + f1 * v.y;
        h[3] = f2 * v.y + f0 * v.z;
        h[4] = f3 * v.y + f1 * v.z;
        h[5] = f2 * v.z + f0 * v.w;
        h[6] = f3 * v.z + f1 * v.w;
        h[7] = f2 * v.w + f0 * q;
    };

    // Vertical combine + store two output rows built from (ha, hb, hc) =
    // h(r-1), h(r), h(r+1) at output rows 2r, 2r+1.
    auto emit = [&](int r, const float h_a[8], const float h_b[8], const float h_c[8]) {
        float4 e0, e1, o0, o1;
        e0.x = g3 * h_a[0] + h_b[0];
        e0.y = g3 * h_a[1] + h_b[1];
        e0.z = g3 * h_a[2] + h_b[2];
        e0.w = g3 * h_a[3] + h_b[3];
        e1.x = g3 * h_a[4] + h_b[4];
        e1.y = g3 * h_a[5] + h_b[5];
        e1.z = g3 * h_a[6] + h_b[6];
        e1.w = g3 * h_a[7] + h_b[7];
        o0.x = g2 * h_b[0] + g0 * h_c[0];
        o0.y = g2 * h_b[1] + g0 * h_c[1];
        o0.z = g2 * h_b[2] + g0 * h_c[2];
        o0.w = g2 * h_b[3] + g0 * h_c[3];
        o1.x = g2 * h_b[4] + g0 * h_c[4];
        o1.y = g2 * h_b[5] + g0 * h_c[5];
        o1.z = g2 * h_b[6] + g0 * h_c[6];
        o1.w = g2 * h_b[7] + g0 * h_c[7];

        const int oc = 8 * lane;
        float* re = op + (size_t)(2 * r) * OW + oc;
        float* ro = op + (size_t)(2 * r + 1) * OW + oc;
        __stcs((float4*)(re),     e0);
        __stcs((float4*)(re + 4), e1);
        __stcs((float4*)(ro),     o0);
        __stcs((float4*)(ro + 4), o1);
    };

    float hprev[8], hcur[8], hn1[8], hn2[8];
    {
        float4 va = load_raw(r0 - 1);
        float4 vb = load_raw(r0);
        hconv(va, hprev);
        hconv(vb, hcur);
    }

#pragma unroll 2
    for (int i = 0; i < RPW; i += 2) {
        const int r = r0 + i;
        // two independent loads issued back-to-back
        float4 v1 = load_raw(r + 1);
        float4 v2 = load_raw(r + 2);
        hconv(v1, hn1);
        hconv(v2, hn2);

        emit(r,     hprev, hcur, hn1);   // output rows 2r,   2r+1
        emit(r + 1, hcur,  hn1,  hn2);   // output rows 2r+2, 2r+3

#pragma unroll
        for (int j = 0; j < 8; j++) { hprev[j] = hn1[j]; hcur[j] = hn2[j]; }
    }
}

extern "C" void kernel_launch(void* const* d_in, const int* in_sizes, int n_in,
                              void* d_out, int out_size) {
    const float* x = (const float*)d_in[0];
    const float* k = (const float*)d_in[1];
    float* out = (float*)d_out;

    const int planes = in_sizes[0] / (H * W);   // 2048
    fir_up2_kernel<<<planes, 256>>>(x, k, out);
}

// round 7
// speedup vs baseline: 1.0491x; 1.0491x over previous
#include <cuda_runtime.h>
#include <cuda_bf16.h>

// upfirdn2d: up=2, down=1, pad=(2,1), 4x4 separable FIR (rank-1: K = g x f).
// Input 2048 planes of 128x128 f32 -> Output 2048 planes of 256x256 f32.
//
// Per-dim half-phase taps (true conv on zero-inserted, padded signal):
//   even o: f[3]*x[o/2-1] + f[1]*x[o/2]
//   odd  o: f[2]*x[(o-1)/2] + f[0]*x[(o+1)/2]
// Horizontal half-conv per input row -> h[8], then vertical combine:
//   out row 2r   = g3*h(r-1) + h(r)          (g1 normalized to 1)
//   out row 2r+1 = g2*h(r)   + g0*h(r+1)
//
// One warp spans a FULL input row (32 lanes x float4 = 128 cols): horizontal
// halo is pure warp-shuffle; lanes 0/31 see the true zero pad. Each block
// processes TWO planes; every loop iteration issues two independent
// LDG.128 (one per plane) -> guaranteed MLP=2 per warp without relying on
// cross-iteration scheduling.

#define H   128
#define W   128
#define OW  256
#define RPW 16   // input rows per warp

struct H8 { float4 lo, hi; };

__global__ __launch_bounds__(256) void fir_up2_kernel(
    const float* __restrict__ x,
    const float* __restrict__ kern,
    float* __restrict__ out)
{
    const int pp    = blockIdx.x;          // plane pair
    const int warp  = threadIdx.x >> 5;
    const int lane  = threadIdx.x & 31;
    const int r0    = warp * RPW;          // 8 warps x 16 rows = 128
    const int c0    = lane * 4;            // input col of v.x

    const float* __restrict__ xa = x + (size_t)(2 * pp)     * (H * W);
    const float* __restrict__ xb = x + (size_t)(2 * pp + 1) * (H * W);
    float* __restrict__ oa = out + (size_t)(2 * pp)     * (OW * 2 * H);
    float* __restrict__ ob = out + (size_t)(2 * pp + 1) * (OW * 2 * H);

    // taps (rank-1 factorization of the 4x4 kernel)
    const float f0 = __ldg(kern + 4 + 0);
    const float f1 = __ldg(kern + 4 + 1);
    const float f2 = __ldg(kern + 4 + 2);
    const float f3 = __ldg(kern + 4 + 3);
    const float inv = 1.0f / f1;
    const float g0 = __ldg(kern + 0 * 4 + 1) * inv;
    const float g2 = __ldg(kern + 2 * 4 + 1) * inv;
    const float g3 = __ldg(kern + 3 * 4 + 1) * inv;

    auto load_raw = [&](const float* __restrict__ xp, int r) -> float4 {
        if (r < 0 || r >= H) return make_float4(0.f, 0.f, 0.f, 0.f);
        return __ldcs((const float4*)(xp + r * W + c0));
    };

    // Horizontal half-convolution of one raw row -> 8 output-col values.
    auto hconv = [&](float4 v) -> H8 {
        float m = __shfl_up_sync(0xffffffffu, v.w, 1);
        if (lane == 0) m = 0.0f;               // true left zero-pad
        float q = __shfl_down_sync(0xffffffffu, v.x, 1);
        if (lane == 31) q = 0.0f;              // true right zero-pad
        H8 h;
        h.lo.x = f3 * m   + f1 * v.x;
        h.lo.y = f2 * v.x + f0 * v.y;
        h.lo.z = f3 * v.x + f1 * v.y;
        h.lo.w = f2 * v.y + f0 * v.z;
        h.hi.x = f3 * v.y + f1 * v.z;
        h.hi.y = f2 * v.z + f0 * v.w;
        h.hi.z = f3 * v.z + f1 * v.w;
        h.hi.w = f2 * v.w + f0 * q;
        return h;
    };

    // Vertical combine + store output rows 2r, 2r+1 of one plane.
    auto emit = [&](float* __restrict__ op, int r,
                    const H8& ha, const H8& hb, const H8& hc) {
        float4 e0, e1, o0, o1;
        e0.x = g3 * ha.lo.x + hb.lo.x;
        e0.y = g3 * ha.lo.y + hb.lo.y;
        e0.z = g3 * ha.lo.z + hb.lo.z;
        e0.w = g3 * ha.lo.w + hb.lo.w;
        e1.x = g3 * ha.hi.x + hb.hi.x;
        e1.y = g3 * ha.hi.y + hb.hi.y;
        e1.z = g3 * ha.hi.z + hb.hi.z;
        e1.w = g3 * ha.hi.w + hb.hi.w;
        o0.x = g2 * hb.lo.x + g0 * hc.lo.x;
        o0.y = g2 * hb.lo.y + g0 * hc.lo.y;
        o0.z = g2 * hb.lo.z + g0 * hc.lo.z;
        o0.w = g2 * hb.lo.w + g0 * hc.lo.w;
        o1.x = g2 * hb.hi.x + g0 * hc.hi.x;
        o1.y = g2 * hb.hi.y + g0 * hc.hi.y;
        o1.z = g2 * hb.hi.z + g0 * hc.hi.z;
        o1.w = g2 * hb.hi.w + g0 * hc.hi.w;

        const int oc = 8 * lane;
        float* re = op + (size_t)(2 * r) * OW + oc;
        float* ro = op + (size_t)(2 * r + 1) * OW + oc;
        __stcs((float4*)(re),     e0);
        __stcs((float4*)(re + 4), e1);
        __stcs((float4*)(ro),     o0);
        __stcs((float4*)(ro + 4), o1);
    };

    // prologue: rows r0-1, r0 for both planes (4 independent loads)
    float4 va0 = load_raw(xa, r0 - 1);
    float4 vb0 = load_raw(xb, r0 - 1);
    float4 va1 = load_raw(xa, r0);
    float4 vb1 = load_raw(xb, r0);
    H8 hprev_a = hconv(va0);
    H8 hprev_b = hconv(vb0);
    H8 hcur_a  = hconv(va1);
    H8 hcur_b  = hconv(vb1);

#pragma unroll 4
    for (int i = 0; i < RPW; i++) {
        const int r = r0 + i;
        float4 va = load_raw(xa, r + 1);   // two independent streams
        float4 vb = load_raw(xb, r + 1);
        H8 hna = hconv(va);
        H8 hnb = hconv(vb);

        emit(oa, r, hprev_a, hcur_a, hna);
        emit(ob, r, hprev_b, hcur_b, hnb);

        hprev_a = hcur_a; hcur_a = hna;
        hprev_b = hcur_b; hcur_b = hnb;
    }
}

extern "C" void kernel_launch(void* const* d_in, const int* in_sizes, int n_in,
                              void* d_out, int out_size) {
    const float* x = (const float*)d_in[0];
    const float* k = (const float*)d_in[1];
    float* out = (float*)d_out;

    const int planes = in_sizes[0] / (H * W);   // 2048
    fir_up2_kernel<<<planes / 2, 256>>>(x, k, out);
}

// round 8
// speedup vs baseline: 1.3063x; 1.2452x over previous
#include <cuda_runtime.h>
#include <cuda_bf16.h>
#include <cstdint>

// upfirdn2d: up=2, down=1, pad=(2,1), 4x4 separable FIR (rank-1: K = g x f).
// Input 2048 planes of 128x128 f32 -> Output 2048 planes of 256x256 f32.
//
// Compute identical to the 118us champion (one warp spans a full input row,
// halo via shuffles, rolling 16-row strip). Store path replaced: each warp
// stages 2 output rows (2KB, contiguous in gmem) in a private SMEM double
// buffer and issues cp.async.bulk.global.shared::cta (UBLKCP) -> big
// contiguous bursts via the copy engine instead of 4x STG.128 per iter.

#define H   128
#define W   128
#define OW  256
#define RPW 16   // input rows per warp

__global__ __launch_bounds__(256) void fir_up2_kernel(
    const float* __restrict__ x,
    const float* __restrict__ kern,
    float* __restrict__ out)
{
    // [warp][buf][2 output rows x 256 f32] = 8 * 2 * 2KB = 32KB
    __shared__ __align__(16) float stage[8][2][2 * OW];

    const int plane = blockIdx.x;
    const int warp  = threadIdx.x >> 5;
    const int lane  = threadIdx.x & 31;
    const int r0    = warp * RPW;          // 8 warps x 16 rows = 128
    const int c0    = lane * 4;            // input col of v.x

    const float* __restrict__ xp = x + (size_t)plane * (H * W);
    float* __restrict__ op = out + (size_t)plane * (OW * 2 * H);

    // taps (rank-1 factorization of the 4x4 kernel)
    const float f0 = __ldg(kern + 4 + 0);
    const float f1 = __ldg(kern + 4 + 1);
    const float f2 = __ldg(kern + 4 + 2);
    const float f3 = __ldg(kern + 4 + 3);
    const float inv = 1.0f / f1;
    const float g0 = __ldg(kern + 0 * 4 + 1) * inv;
    const float g2 = __ldg(kern + 2 * 4 + 1) * inv;
    const float g3 = __ldg(kern + 3 * 4 + 1) * inv;

    // Load one full input row (LDG.128/lane) + horizontal half-conv -> h[8].
    auto loadh = [&](int r, float h[8]) {
        if (r < 0 || r >= H) {
#pragma unroll
            for (int j = 0; j < 8; j++) h[j] = 0.0f;
            return;
        }
        float4 v = __ldcs((const float4*)(xp + r * W + c0));
        float m = __shfl_up_sync(0xffffffffu, v.w, 1);
        if (lane == 0) m = 0.0f;               // true left zero-pad
        float q = __shfl_down_sync(0xffffffffu, v.x, 1);
        if (lane == 31) q = 0.0f;              // true right zero-pad
        h[0] = f3 * m   + f1 * v.x;
        h[1] = f2 * v.x + f0 * v.y;
        h[2] = f3 * v.x + f1 * v.y;
        h[3] = f2 * v.y + f0 * v.z;
        h[4] = f3 * v.y + f1 * v.z;
        h[5] = f2 * v.z + f0 * v.w;
        h[6] = f3 * v.z + f1 * v.w;
        h[7] = f2 * v.w + f0 * q;
    };

    float hprev[8], hcur[8], hnxt[8];
    loadh(r0 - 1, hprev);
    loadh(r0,     hcur);

    const int oc = 8 * lane;

#pragma unroll 4
    for (int i = 0; i < RPW; i++) {
        const int r = r0 + i;
        const int buf = i & 1;

        // Before refilling this buffer, make sure its previous bulk read
        // (issued 2 iterations ago by lane 0) has completed.
        if (i >= 2) {
            if (lane == 0)
                asm volatile("cp.async.bulk.wait_group.read 1;" ::: "memory");
            __syncwarp();
        }

        loadh(r + 1, hnxt);

        float4 e0, e1, o0, o1;
        e0.x = g3 * hprev[0] + hcur[0];
        e0.y = g3 * hprev[1] + hcur[1];
        e0.z = g3 * hprev[2] + hcur[2];
        e0.w = g3 * hprev[3] + hcur[3];
        e1.x = g3 * hprev[4] + hcur[4];
        e1.y = g3 * hprev[5] + hcur[5];
        e1.z = g3 * hprev[6] + hcur[6];
        e1.w = g3 * hprev[7] + hcur[7];
        o0.x = g2 * hcur[0] + g0 * hnxt[0];
        o0.y = g2 * hcur[1] + g0 * hnxt[1];
        o0.z = g2 * hcur[2] + g0 * hnxt[2];
        o0.w = g2 * hcur[3] + g0 * hnxt[3];
        o1.x = g2 * hcur[4] + g0 * hnxt[4];
        o1.y = g2 * hcur[5] + g0 * hnxt[5];
        o1.z = g2 * hcur[6] + g0 * hnxt[6];
        o1.w = g2 * hcur[7] + g0 * hnxt[7];

        float* sb = &stage[warp][buf][0];
        *(float4*)(sb + oc)           = e0;   // even output row
        *(float4*)(sb + oc + 4)       = e1;
        *(float4*)(sb + OW + oc)      = o0;   // odd output row
        *(float4*)(sb + OW + oc + 4)  = o1;

        // Order the STS against the async proxy, then one lane fires the
        // 2KB contiguous bulk store (output rows 2r, 2r+1).
        asm volatile("fence.proxy.async.shared::cta;" ::: "memory");
        __syncwarp();
        if (lane == 0) {
            uint32_t saddr = (uint32_t)__cvta_generic_to_shared(sb);
            float* gdst = op + (size_t)(2 * r) * OW;
            asm volatile(
                "cp.async.bulk.global.shared::cta.bulk_group [%0], [%1], %2;"
                :: "l"(gdst), "r"(saddr), "r"(2 * OW * 4) : "memory");
            asm volatile("cp.async.bulk.commit_group;" ::: "memory");
        }

#pragma unroll
        for (int j = 0; j < 8; j++) { hprev[j] = hcur[j]; hcur[j] = hnxt[j]; }
    }

    // Drain all outstanding bulk stores before exit.
    if (lane == 0)
        asm volatile("cp.async.bulk.wait_group 0;" ::: "memory");
}

extern "C" void kernel_launch(void* const* d_in, const int* in_sizes, int n_in,
                              void* d_out, int out_size) {
    const float* x = (const float*)d_in[0];
    const float* k = (const float*)d_in[1];
    float* out = (float*)d_out;

    const int planes = in_sizes[0] / (H * W);   // 2048
    fir_up2_kernel<<<planes, 256>>>(x, k, out);
}

// round 9
// speedup vs baseline: 1.3292x; 1.0176x over previous
#include <cuda_runtime.h>
#include <cuda_bf16.h>
#include <cstdint>

// upfirdn2d: up=2, down=1, pad=(2,1), 4x4 separable FIR (rank-1: K = g x f).
// Input 2048 planes of 128x128 f32 -> Output 2048 planes of 256x256 f32.
//
// Compute as the 118us champion (one warp spans a full input row, halo via
// shuffles, rolling 16-row strip). Store path: each warp stages FOUR output
// rows (4KB contiguous) per stage in a double-buffered SMEM ring and fires
// one cp.async.bulk S2G (UBLKCP) per stage -> half the fence/commit/elect
// overhead of the 2KB version, up to 8KB outstanding per warp.

#define H   128
#define W   128
#define OW  256
#define RPW 16   // input rows per warp

__global__ __launch_bounds__(256) void fir_up2_kernel(
    const float* __restrict__ x,
    const float* __restrict__ kern,
    float* __restrict__ out)
{
    // [warp][buf][4 output rows x 256 f32] = 8 * 2 * 4KB = 64KB
    __shared__ __align__(16) float stage[8][2][4 * OW];

    const int plane = blockIdx.x;
    const int warp  = threadIdx.x >> 5;
    const int lane  = threadIdx.x & 31;
    const int r0    = warp * RPW;          // 8 warps x 16 rows = 128
    const int c0    = lane * 4;            // input col of v.x

    const float* __restrict__ xp = x + (size_t)plane * (H * W);
    float* __restrict__ op = out + (size_t)plane * (OW * 2 * H);

    // taps (rank-1 factorization of the 4x4 kernel)
    const float f0 = __ldg(kern + 4 + 0);
    const float f1 = __ldg(kern + 4 + 1);
    const float f2 = __ldg(kern + 4 + 2);
    const float f3 = __ldg(kern + 4 + 3);
    const float inv = 1.0f / f1;
    const float g0 = __ldg(kern + 0 * 4 + 1) * inv;
    const float g2 = __ldg(kern + 2 * 4 + 1) * inv;
    const float g3 = __ldg(kern + 3 * 4 + 1) * inv;

    // Load one full input row (LDG.128/lane) + horizontal half-conv -> h[8].
    auto loadh = [&](int r, float h[8]) {
        if (r < 0 || r >= H) {
#pragma unroll
            for (int j = 0; j < 8; j++) h[j] = 0.0f;
            return;
        }
        float4 v = __ldcs((const float4*)(xp + r * W + c0));
        float m = __shfl_up_sync(0xffffffffu, v.w, 1);
        if (lane == 0) m = 0.0f;               // true left zero-pad
        float q = __shfl_down_sync(0xffffffffu, v.x, 1);
        if (lane == 31) q = 0.0f;              // true right zero-pad
        h[0] = f3 * m   + f1 * v.x;
        h[1] = f2 * v.x + f0 * v.y;
        h[2] = f3 * v.x + f1 * v.y;
        h[3] = f2 * v.y + f0 * v.z;
        h[4] = f3 * v.y + f1 * v.z;
        h[5] = f2 * v.z + f0 * v.w;
        h[6] = f3 * v.z + f1 * v.w;
        h[7] = f2 * v.w + f0 * q;
    };

    // Vertical combine rows (ha=h(r-1), hb=h(r), hc=h(r+1)) -> SMEM at rows
    // (2*local, 2*local+1) of the current stage buffer.
    auto emit_smem = [&](float* sb, int local,
                         const float ha[8], const float hb[8], const float hc[8]) {
        float4 e0, e1, o0, o1;
        e0.x = g3 * ha[0] + hb[0];
        e0.y = g3 * ha[1] + hb[1];
        e0.z = g3 * ha[2] + hb[2];
        e0.w = g3 * ha[3] + hb[3];
        e1.x = g3 * ha[4] + hb[4];
        e1.y = g3 * ha[5] + hb[5];
        e1.z = g3 * ha[6] + hb[6];
        e1.w = g3 * ha[7] + hb[7];
        o0.x = g2 * hb[0] + g0 * hc[0];
        o0.y = g2 * hb[1] + g0 * hc[1];
        o0.z = g2 * hb[2] + g0 * hc[2];
        o0.w = g2 * hb[3] + g0 * hc[3];
        o1.x = g2 * hb[4] + g0 * hc[4];
        o1.y = g2 * hb[5] + g0 * hc[5];
        o1.z = g2 * hb[6] + g0 * hc[6];
        o1.w = g2 * hb[7] + g0 * hc[7];
        const int oc = 8 * lane;
        float* re = sb + (2 * local) * OW + oc;
        float* ro = sb + (2 * local + 1) * OW + oc;
        *(float4*)(re)     = e0;
        *(float4*)(re + 4) = e1;
        *(float4*)(ro)     = o0;
        *(float4*)(ro + 4) = o1;
    };

    float hprev[8], hcur[8], hn1[8], hn2[8];
    loadh(r0 - 1, hprev);
    loadh(r0,     hcur);

#pragma unroll 2
    for (int i = 0; i < RPW; i += 2) {
        const int r = r0 + i;
        const int buf = (i >> 1) & 1;

        // Reuse guard: buffer was handed to the copy engine 2 stages ago.
        if (i >= 4) {
            if (lane == 0)
                asm volatile("cp.async.bulk.wait_group.read 1;" ::: "memory");
            __syncwarp();
        }

        // two row loads of this stage issued close together
        loadh(r + 1, hn1);
        loadh(r + 2, hn2);

        float* sb = &stage[warp][buf][0];
        emit_smem(sb, 0, hprev, hcur, hn1);   // output rows 2r,   2r+1
        emit_smem(sb, 1, hcur,  hn1,  hn2);   // output rows 2r+2, 2r+3

        // Order STS vs async proxy; elect one lane to fire the 4KB burst.
        asm volatile("fence.proxy.async.shared::cta;" ::: "memory");
        __syncwarp();
        if (lane == 0) {
            uint32_t saddr = (uint32_t)__cvta_generic_to_shared(sb);
            float* gdst = op + (size_t)(2 * r) * OW;
            asm volatile(
                "cp.async.bulk.global.shared::cta.bulk_group [%0], [%1], %2;"
                :: "l"(gdst), "r"(saddr), "r"(4 * OW * 4) : "memory");
            asm volatile("cp.async.bulk.commit_group;" ::: "memory");
        }

#pragma unroll
        for (int j = 0; j < 8; j++) { hprev[j] = hn1[j]; hcur[j] = hn2[j]; }
    }

    // Drain all outstanding bulk stores before exit.
    if (lane == 0)
        asm volatile("cp.async.bulk.wait_group 0;" ::: "memory");
}

extern "C" void kernel_launch(void* const* d_in, const int* in_sizes, int n_in,
                              void* d_out, int out_size) {
    const float* x = (const float*)d_in[0];
    const float* k = (const float*)d_in[1];
    float* out = (float*)d_out;

    const int planes = in_sizes[0] / (H * W);   // 2048
    fir_up2_kernel<<<planes, 256>>>(x, k, out);
}

// round 10
// speedup vs baseline: 1.3733x; 1.0331x over previous
#include <cuda_runtime.h>
#include <cuda_bf16.h>
#include <cstdint>

// upfirdn2d: up=2, down=1, pad=(2,1), 4x4 separable FIR (rank-1: K = g x f).
// Input 2048 planes of 128x128 f32 -> Output 2048 planes of 256x256 f32.
//
// One warp spans a full input row (32 lanes x float4 = 128 cols; halo via
// shuffles, true zero-pad at lanes 0/31). Each warp rolls a 16-row strip,
// 2 rows per stage. Raw row loads are software-pipelined ONE STAGE AHEAD
// (MLP=4/warp) so DRAM read latency overlaps the STS/fence/bulk-store work.
// Stores: 4 output rows (4KB contiguous) staged in a double-buffered SMEM
// ring, flushed with cp.async.bulk S2G (UBLKCP) by an elected lane.

#define H   128
#define W   128
#define OW  256
#define RPW 16   // input rows per warp

__global__ __launch_bounds__(256, 3) void fir_up2_kernel(
    const float* __restrict__ x,
    const float* __restrict__ kern,
    float* __restrict__ out)
{
    // [warp][buf][4 output rows x 256 f32] = 8 * 2 * 4KB = 64KB
    __shared__ __align__(16) float stage[8][2][4 * OW];

    const int plane = blockIdx.x;
    const int warp  = threadIdx.x >> 5;
    const int lane  = threadIdx.x & 31;
    const int r0    = warp * RPW;          // 8 warps x 16 rows = 128
    const int c0    = lane * 4;            // input col of v.x

    const float* __restrict__ xp = x + (size_t)plane * (H * W);
    float* __restrict__ op = out + (size_t)plane * (OW * 2 * H);

    // taps (rank-1 factorization of the 4x4 kernel)
    const float f0 = __ldg(kern + 4 + 0);
    const float f1 = __ldg(kern + 4 + 1);
    const float f2 = __ldg(kern + 4 + 2);
    const float f3 = __ldg(kern + 4 + 3);
    const float inv = 1.0f / f1;
    const float g0 = __ldg(kern + 0 * 4 + 1) * inv;
    const float g2 = __ldg(kern + 2 * 4 + 1) * inv;
    const float g3 = __ldg(kern + 3 * 4 + 1) * inv;

    auto load_raw = [&](int r) -> float4 {
        if (r < 0 || r >= H) return make_float4(0.f, 0.f, 0.f, 0.f);
        return __ldcs((const float4*)(xp + r * W + c0));
    };

    // Horizontal half-convolution of one raw row -> 8 output-col values.
    auto hconv = [&](float4 v, float h[8]) {
        float m = __shfl_up_sync(0xffffffffu, v.w, 1);
        if (lane == 0) m = 0.0f;               // true left zero-pad
        float q = __shfl_down_sync(0xffffffffu, v.x, 1);
        if (lane == 31) q = 0.0f;              // true right zero-pad
        h[0] = f3 * m   + f1 * v.x;
        h[1] = f2 * v.x + f0 * v.y;
        h[2] = f3 * v.x + f1 * v.y;
        h[3] = f2 * v.y + f0 * v.z;
        h[4] = f3 * v.y + f1 * v.z;
        h[5] = f2 * v.z + f0 * v.w;
        h[6] = f3 * v.z + f1 * v.w;
        h[7] = f2 * v.w + f0 * q;
    };

    // Vertical combine (ha=h(r-1), hb=h(r), hc=h(r+1)) -> SMEM stage rows.
    auto emit_smem = [&](float* sb, int local,
                         const float ha[8], const float hb[8], const float hc[8]) {
        float4 e0, e1, o0, o1;
        e0.x = g3 * ha[0] + hb[0];
        e0.y = g3 * ha[1] + hb[1];
        e0.z = g3 * ha[2] + hb[2];
        e0.w = g3 * ha[3] + hb[3];
        e1.x = g3 * ha[4] + hb[4];
        e1.y = g3 * ha[5] + hb[5];
        e1.z = g3 * ha[6] + hb[6];
        e1.w = g3 * ha[7] + hb[7];
        o0.x = g2 * hb[0] + g0 * hc[0];
        o0.y = g2 * hb[1] + g0 * hc[1];
        o0.z = g2 * hb[2] + g0 * hc[2];
        o0.w = g2 * hb[3] + g0 * hc[3];
        o1.x = g2 * hb[4] + g0 * hc[4];
        o1.y = g2 * hb[5] + g0 * hc[5];
        o1.z = g2 * hb[6] + g0 * hc[6];
        o1.w = g2 * hb[7] + g0 * hc[7];
        const int oc = 8 * lane;
        float* re = sb + (2 * local) * OW + oc;
        float* ro = sb + (2 * local + 1) * OW + oc;
        *(float4*)(re)     = e0;
        *(float4*)(re + 4) = e1;
        *(float4*)(ro)     = o0;
        *(float4*)(ro + 4) = o1;
    };

    float hprev[8], hcur[8], hn1[8], hn2[8];
    hconv(load_raw(r0 - 1), hprev);
    hconv(load_raw(r0),     hcur);

    // raw rows for the CURRENT stage (r+1, r+2), prefetched
    float4 v1 = load_raw(r0 + 1);
    float4 v2 = load_raw(r0 + 2);

#pragma unroll 2
    for (int i = 0; i < RPW; i += 2) {
        const int r = r0 + i;
        const int buf = (i >> 1) & 1;

        // Prefetch NEXT stage's raw rows first: in flight while this stage
        // computes, stores to SMEM, and issues its bulk copy.
        float4 p1 = load_raw(r + 3);
        float4 p2 = load_raw(r + 4);

        // Reuse guard: buffer was handed to the copy engine 2 stages ago.
        if (i >= 4) {
            if (lane == 0)
                asm volatile("cp.async.bulk.wait_group.read 1;" ::: "memory");
            __syncwarp();
        }

        hconv(v1, hn1);
        hconv(v2, hn2);

        float* sb = &stage[warp][buf][0];
        emit_smem(sb, 0, hprev, hcur, hn1);   // output rows 2r,   2r+1
        emit_smem(sb, 1, hcur,  hn1,  hn2);   // output rows 2r+2, 2r+3

        // Order STS vs async proxy; elect one lane to fire the 4KB burst.
        asm volatile("fence.proxy.async.shared::cta;" ::: "memory");
        __syncwarp();
        if (lane == 0) {
            uint32_t saddr = (uint32_t)__cvta_generic_to_shared(sb);
            float* gdst = op + (size_t)(2 * r) * OW;
            asm volatile(
                "cp.async.bulk.global.shared::cta.bulk_group [%0], [%1], %2;"
                :: "l"(gdst), "r"(saddr), "r"(4 * OW * 4) : "memory");
            asm volatile("cp.async.bulk.commit_group;" ::: "memory");
        }

#pragma unroll
        for (int j = 0; j < 8; j++) { hprev[j] = hn1[j]; hcur[j] = hn2[j]; }
        v1 = p1;
        v2 = p2;
    }

    // Drain all outstanding bulk stores before exit.
    if (lane == 0)
        asm volatile("cp.async.bulk.wait_group 0;" ::: "memory");
}

extern "C" void kernel_launch(void* const* d_in, const int* in_sizes, int n_in,
                              void* d_out, int out_size) {
    const float* x = (const float*)d_in[0];
    const float* k = (const float*)d_in[1];
    float* out = (float*)d_out;

    const int planes = in_sizes[0] / (H * W);   // 2048
    fir_up2_kernel<<<planes, 256>>>(x, k, out);
}

// round 11
// speedup vs baseline: 1.3788x; 1.0040x over previous
#include <cuda_runtime.h>
#include <cuda_bf16.h>
#include <cstdint>

// upfirdn2d: up=2, down=1, pad=(2,1), 4x4 separable FIR (rank-1: K = g x f).
// Input 2048 planes of 128x128 f32 -> Output 2048 planes of 256x256 f32.
//
// One warp spans a full input row (32 lanes x float4 = 128 cols; halo via
// shuffles, true zero-pad at lanes 0/31). Each warp rolls a 16-row strip,
// 2 rows per stage. Raw row loads are software-pipelined TWO STAGES AHEAD
// (MLP=6/warp) so DRAM read latency overlaps compute + store issue of two
// stages. Stores: 4 output rows (4KB contiguous) staged in a double-buffered
// SMEM ring, flushed with cp.async.bulk S2G (UBLKCP) by an elected lane.

#define H   128
#define W   128
#define OW  256
#define RPW 16   // input rows per warp

__global__ __launch_bounds__(256, 3) void fir_up2_kernel(
    const float* __restrict__ x,
    const float* __restrict__ kern,
    float* __restrict__ out)
{
    // [warp][buf][4 output rows x 256 f32] = 8 * 2 * 4KB = 64KB
    __shared__ __align__(16) float stage[8][2][4 * OW];

    const int plane = blockIdx.x;
    const int warp  = threadIdx.x >> 5;
    const int lane  = threadIdx.x & 31;
    const int r0    = warp * RPW;          // 8 warps x 16 rows = 128
    const int c0    = lane * 4;            // input col of v.x

    const float* __restrict__ xp = x + (size_t)plane * (H * W);
    float* __restrict__ op = out + (size_t)plane * (OW * 2 * H);

    // taps (rank-1 factorization of the 4x4 kernel)
    const float f0 = __ldg(kern + 4 + 0);
    const float f1 = __ldg(kern + 4 + 1);
    const float f2 = __ldg(kern + 4 + 2);
    const float f3 = __ldg(kern + 4 + 3);
    const float inv = 1.0f / f1;
    const float g0 = __ldg(kern + 0 * 4 + 1) * inv;
    const float g2 = __ldg(kern + 2 * 4 + 1) * inv;
    const float g3 = __ldg(kern + 3 * 4 + 1) * inv;

    // Default-cached load: halo rows are re-read by the adjacent warp, let
    // them hit L1/L2 (evict-first was wasting that reuse).
    auto load_raw = [&](int r) -> float4 {
        if (r < 0 || r >= H) return make_float4(0.f, 0.f, 0.f, 0.f);
        return *(const float4*)(xp + r * W + c0);
    };

    // Horizontal half-convolution of one raw row -> 8 output-col values.
    auto hconv = [&](float4 v, float h[8]) {
        float m = __shfl_up_sync(0xffffffffu, v.w, 1);
        if (lane == 0) m = 0.0f;               // true left zero-pad
        float q = __shfl_down_sync(0xffffffffu, v.x, 1);
        if (lane == 31) q = 0.0f;              // true right zero-pad
        h[0] = f3 * m   + f1 * v.x;
        h[1] = f2 * v.x + f0 * v.y;
        h[2] = f3 * v.x + f1 * v.y;
        h[3] = f2 * v.y + f0 * v.z;
        h[4] = f3 * v.y + f1 * v.z;
        h[5] = f2 * v.z + f0 * v.w;
        h[6] = f3 * v.z + f1 * v.w;
        h[7] = f2 * v.w + f0 * q;
    };

    // Vertical combine (ha=h(r-1), hb=h(r), hc=h(r+1)) -> SMEM stage rows.
    auto emit_smem = [&](float* sb, int local,
                         const float ha[8], const float hb[8], const float hc[8]) {
        float4 e0, e1, o0, o1;
        e0.x = g3 * ha[0] + hb[0];
        e0.y = g3 * ha[1] + hb[1];
        e0.z = g3 * ha[2] + hb[2];
        e0.w = g3 * ha[3] + hb[3];
        e1.x = g3 * ha[4] + hb[4];
        e1.y = g3 * ha[5] + hb[5];
        e1.z = g3 * ha[6] + hb[6];
        e1.w = g3 * ha[7] + hb[7];
        o0.x = g2 * hb[0] + g0 * hc[0];
        o0.y = g2 * hb[1] + g0 * hc[1];
        o0.z = g2 * hb[2] + g0 * hc[2];
        o0.w = g2 * hb[3] + g0 * hc[3];
        o1.x = g2 * hb[4] + g0 * hc[4];
        o1.y = g2 * hb[5] + g0 * hc[5];
        o1.z = g2 * hb[6] + g0 * hc[6];
        o1.w = g2 * hb[7] + g0 * hc[7];
        const int oc = 8 * lane;
        float* re = sb + (2 * local) * OW + oc;
        float* ro = sb + (2 * local + 1) * OW + oc;
        *(float4*)(re)     = e0;
        *(float4*)(re + 4) = e1;
        *(float4*)(ro)     = o0;
        *(float4*)(ro + 4) = o1;
    };

    float hprev[8], hcur[8], hn1[8], hn2[8];
    hconv(load_raw(r0 - 1), hprev);
    hconv(load_raw(r0),     hcur);

    // pipeline: v = current stage raw rows, p = next stage raw rows
    float4 v1 = load_raw(r0 + 1);
    float4 v2 = load_raw(r0 + 2);
    float4 p1 = load_raw(r0 + 3);
    float4 p2 = load_raw(r0 + 4);

#pragma unroll 2
    for (int i = 0; i < RPW; i += 2) {
        const int r = r0 + i;
        const int buf = (i >> 1) & 1;

        // Issue loads for stage i+2 first: in flight across two full stages.
        float4 q1 = load_raw(r + 5);
        float4 q2 = load_raw(r + 6);

        // Reuse guard: buffer was handed to the copy engine 2 stages ago.
        if (i >= 4) {
            if (lane == 0)
                asm volatile("cp.async.bulk.wait_group.read 1;" ::: "memory");
            __syncwarp();
        }

        hconv(v1, hn1);
        hconv(v2, hn2);

        float* sb = &stage[warp][buf][0];
        emit_smem(sb, 0, hprev, hcur, hn1);   // output rows 2r,   2r+1
        emit_smem(sb, 1, hcur,  hn1,  hn2);   // output rows 2r+2, 2r+3

        // Order STS vs async proxy; elect one lane to fire the 4KB burst.
        asm volatile("fence.proxy.async.shared::cta;" ::: "memory");
        __syncwarp();
        if (lane == 0) {
            uint32_t saddr = (uint32_t)__cvta_generic_to_shared(sb);
            float* gdst = op + (size_t)(2 * r) * OW;
            asm volatile(
                "cp.async.bulk.global.shared::cta.bulk_group [%0], [%1], %2;"
                :: "l"(gdst), "r"(saddr), "r"(4 * OW * 4) : "memory");
            asm volatile("cp.async.bulk.commit_group;" ::: "memory");
        }

#pragma unroll
        for (int j = 0; j < 8; j++) { hprev[j] = hn1[j]; hcur[j] = hn2[j]; }
        v1 = p1; v2 = p2;
        p1 = q1; p2 = q2;
    }

    // Drain all outstanding bulk stores before exit.
    if (lane == 0)
        asm volatile("cp.async.bulk.wait_group 0;" ::: "memory");
}

extern "C" void kernel_launch(void* const* d_in, const int* in_sizes, int n_in,
                              void* d_out, int out_size) {
    const float* x = (const float*)d_in[0];
    const float* k = (const float*)d_in[1];
    float* out = (float*)d_out;

    const int planes = in_sizes[0] / (H * W);   // 2048
    fir_up2_kernel<<<planes, 256>>>(x, k, out);
}

// round 12
// speedup vs baseline: 1.3991x; 1.0147x over previous
#include <cuda_runtime.h>
#include <cuda_bf16.h>
#include <cstdint>

// upfirdn2d: up=2, down=1, pad=(2,1), 4x4 separable FIR (rank-1: K = g x f).
// Input 2048 planes of 128x128 f32 -> Output 2048 planes of 256x256 f32.
//
// Fully async memory pipeline:
//   reads : per-lane cp.async (LDGSTS, 16B) into a per-warp SMEM ring,
//           depth 4 chunks x 2 rows, consumed 3 chunks behind issue
//           (cp.async.wait_group 3) -> ~6 rows of read lookahead, no
//           long-scoreboard stalls, no register pipeline.
//   writes: 4 output rows (4KB contiguous) staged in a double-buffered
//           SMEM ring, flushed with cp.async.bulk S2G by an elected lane.
// One warp spans a full input row (32 lanes x float4); halo via shuffles,
// true zero-pad at lanes 0/31. 4 warps x 32 rows = one plane per block.

#define H   128
#define W   128
#define OW  256
#define NW  4      // warps per block
#define RPW 32     // input rows per warp
#define NCHUNK (RPW / 2)   // 16 chunks of 2 rows
#define RING 4

__global__ __launch_bounds__(128, 4) void fir_up2_kernel(
    const float* __restrict__ x,
    const float* __restrict__ kern,
    float* __restrict__ out)
{
    __shared__ __align__(16) float inring[NW][RING][2 * W];   // 16KB
    __shared__ __align__(16) float stage[NW][2][4 * OW];      // 32KB

    const int plane = blockIdx.x;
    const int warp  = threadIdx.x >> 5;
    const int lane  = threadIdx.x & 31;
    const int r0    = warp * RPW;          // 4 warps x 32 rows = 128
    const int c0    = lane * 4;            // input col of this lane's float4

    const float* __restrict__ xp = x + (size_t)plane * (H * W);
    float* __restrict__ op = out + (size_t)plane * (OW * 2 * H);

    // taps (rank-1 factorization of the 4x4 kernel)
    const float f0 = __ldg(kern + 4 + 0);
    const float f1 = __ldg(kern + 4 + 1);
    const float f2 = __ldg(kern + 4 + 2);
    const float f3 = __ldg(kern + 4 + 3);
    const float inv = 1.0f / f1;
    const float g0 = __ldg(kern + 0 * 4 + 1) * inv;
    const float g2 = __ldg(kern + 2 * 4 + 1) * inv;
    const float g3 = __ldg(kern + 3 * 4 + 1) * inv;

    // Issue async copy of chunk k (input rows r0+2k+1, r0+2k+2) into ring
    // slot k%RING. Each lane moves only its own 16B per row. OOB rows
    // (beyond H-1, only the last chunk of the last warp) are zero-filled.
    auto issue_chunk = [&](int k) {
        const int s = k & (RING - 1);
#pragma unroll
        for (int j = 0; j < 2; j++) {
            const int r = r0 + 2 * k + 1 + j;
            float* dstp = &inring[warp][s][j * W + c0];
            uint32_t sa = (uint32_t)__cvta_generic_to_shared(dstp);
            if (r < H) {
                const float* src = xp + r * W + c0;
                asm volatile(
                    "cp.async.cg.shared.global [%0], [%1], 16;"
                    :: "r"(sa), "l"(src) : "memory");
            } else {
                *(float4*)dstp = make_float4(0.f, 0.f, 0.f, 0.f);
            }
        }
        asm volatile("cp.async.commit_group;" ::: "memory");
    };

    // Horizontal half-convolution of one raw row -> 8 output-col values.
    auto hconv = [&](float4 v, float h[8]) {
        float m = __shfl_up_sync(0xffffffffu, v.w, 1);
        if (lane == 0) m = 0.0f;               // true left zero-pad
        float q = __shfl_down_sync(0xffffffffu, v.x, 1);
        if (lane == 31) q = 0.0f;              // true right zero-pad
        h[0] = f3 * m   + f1 * v.x;
        h[1] = f2 * v.x + f0 * v.y;
        h[2] = f3 * v.x + f1 * v.y;
        h[3] = f2 * v.y + f0 * v.z;
        h[4] = f3 * v.y + f1 * v.z;
        h[5] = f2 * v.z + f0 * v.w;
        h[6] = f3 * v.z + f1 * v.w;
        h[7] = f2 * v.w + f0 * q;
    };

    // Vertical combine (ha=h(r-1), hb=h(r), hc=h(r+1)) -> SMEM stage rows.
    auto emit_smem = [&](float* sb, int local,
                         const float ha[8], const float hb[8], const float hc[8]) {
        float4 e0, e1, o0, o1;
        e0.x = g3 * ha[0] + hb[0];
        e0.y = g3 * ha[1] + hb[1];
        e0.z = g3 * ha[2] + hb[2];
        e0.w = g3 * ha[3] + hb[3];
        e1.x = g3 * ha[4] + hb[4];
        e1.y = g3 * ha[5] + hb[5];
        e1.z = g3 * ha[6] + hb[6];
        e1.w = g3 * ha[7] + hb[7];
        o0.x = g2 * hb[0] + g0 * hc[0];
        o0.y = g2 * hb[1] + g0 * hc[1];
        o0.z = g2 * hb[2] + g0 * hc[2];
        o0.w = g2 * hb[3] + g0 * hc[3];
        o1.x = g2 * hb[4] + g0 * hc[4];
        o1.y = g2 * hb[5] + g0 * hc[5];
        o1.z = g2 * hb[6] + g0 * hc[6];
        o1.w = g2 * hb[7] + g0 * hc[7];
        const int oc = 8 * lane;
        float* re = sb + (2 * local) * OW + oc;
        float* ro = sb + (2 * local + 1) * OW + oc;
        *(float4*)(re)     = e0;
        *(float4*)(re + 4) = e1;
        *(float4*)(ro)     = o0;
        *(float4*)(ro + 4) = o1;
    };

    // Prologue: halo rows r0-1, r0 via plain LDG (registers);
    // ring chunks 0,1,2 in flight.
    float hprev[8], hcur[8], hn1[8], hn2[8];
    {
        float4 va = (r0 - 1 >= 0) ? *(const float4*)(xp + (r0 - 1) * W + c0)
                                  : make_float4(0.f, 0.f, 0.f, 0.f);
        float4 vb = *(const float4*)(xp + r0 * W + c0);
        hconv(va, hprev);
        hconv(vb, hcur);
    }
    issue_chunk(0);
    issue_chunk(1);
    issue_chunk(2);

#pragma unroll 2
    for (int i = 0; i < NCHUNK; i++) {
        const int r = r0 + 2 * i;
        const int buf = i & 1;

        // Keep the read ring 3 chunks deep (empty commit keeps counts uniform).
        if (i + 3 < NCHUNK) issue_chunk(i + 3);
        else asm volatile("cp.async.commit_group;" ::: "memory");

        // Reuse guard for the output buffer handed to the copy engine 2 stages ago.
        if (i >= 2) {
            if (lane == 0)
                asm volatile("cp.async.bulk.wait_group.read 1;" ::: "memory");
            __syncwarp();
        }

        // Chunk i ready once all but the 3 newest groups have drained.
        asm volatile("cp.async.wait_group 3;" ::: "memory");
        const int s = i & (RING - 1);
        float4 v1 = *(const float4*)&inring[warp][s][0 * W + c0];
        float4 v2 = *(const float4*)&inring[warp][s][1 * W + c0];

        hconv(v1, hn1);
        hconv(v2, hn2);

        float* sb = &stage[warp][buf][0];
        emit_smem(sb, 0, hprev, hcur, hn1);   // output rows 2r,   2r+1
        emit_smem(sb, 1, hcur,  hn1,  hn2);   // output rows 2r+2, 2r+3

        // Order STS vs async proxy; elect one lane to fire the 4KB burst.
        asm volatile("fence.proxy.async.shared::cta;" ::: "memory");
        __syncwarp();
        if (lane == 0) {
            uint32_t saddr = (uint32_t)__cvta_generic_to_shared(sb);
            float* gdst = op + (size_t)(2 * r) * OW;
            asm volatile(
                "cp.async.bulk.global.shared::cta.bulk_group [%0], [%1], %2;"
                :: "l"(gdst), "r"(saddr), "r"(4 * OW * 4) : "memory");
            asm volatile("cp.async.bulk.commit_group;" ::: "memory");
        }

#pragma unroll
        for (int j = 0; j < 8; j++) { hprev[j] = hn1[j]; hcur[j] = hn2[j]; }
    }

    // Drain all outstanding bulk stores before exit.
    if (lane == 0)
        asm volatile("cp.async.bulk.wait_group 0;" ::: "memory");
}

extern "C" void kernel_launch(void* const* d_in, const int* in_sizes, int n_in,
                              void* d_out, int out_size) {
    const float* x = (const float*)d_in[0];
    const float* k = (const float*)d_in[1];
    float* out = (float*)d_out;

    const int planes = in_sizes[0] / (H * W);   // 2048
    fir_up2_kernel<<<planes, 128>>>(x, k, out);
}